// round 14
// baseline (speedup 1.0000x reference)
#include <cuda_runtime.h>
#include <cuda_fp16.h>
#include <math.h>
#include <cstdint>

// Problem shape (fixed)
#define S_TOK 8192
#define MDIM  1024
#define EEXP  8
#define HDIM  4096
#define CAP   1024

// ---------------- device scratch ----------------
__device__ __half g_disp[EEXP * CAP * MDIM];            // 16 MB [E,C,M] fp16
__device__ __half g_h   [(size_t)EEXP * CAP * HDIM];    // 64 MB [E,C,H] fp16
__device__ __half g_w1h [(size_t)EEXP * MDIM * HDIM];   // 64 MB [E,K=M,N=H] fp16
__device__ __half g_w2h [(size_t)EEXP * HDIM * MDIM];   // 64 MB [E,K=H,N=M] fp16
__device__ int    g_eidx[S_TOK];
__device__ float  g_gate[S_TOK];
__device__ float  g_gatef[S_TOK];
__device__ int    g_inv [EEXP * CAP];                   // slot -> token (-1 empty)

// ---------------- helpers ----------------
__device__ __forceinline__ uint32_t smem_u32(const void* p) {
    uint32_t a;
    asm("{ .reg .u64 t; cvta.to.shared.u64 t, %1; cvt.u32.u64 %0, t; }" : "=r"(a) : "l"(p));
    return a;
}
__device__ __forceinline__ void cp_async16(uint32_t dst, const void* src) {
    asm volatile("cp.async.cg.shared.global [%0], [%1], 16;" :: "r"(dst), "l"(src) : "memory");
}
__device__ __forceinline__ void cp_commit() {
    asm volatile("cp.async.commit_group;" ::: "memory");
}
template <int N>
__device__ __forceinline__ void cp_wait() {
    asm volatile("cp.async.wait_group %0;" :: "n"(N) : "memory");
}
__device__ __forceinline__ void ldsm_x4(uint32_t& d0, uint32_t& d1, uint32_t& d2, uint32_t& d3,
                                        uint32_t addr) {
    asm volatile("ldmatrix.sync.aligned.m8n8.x4.shared.b16 {%0,%1,%2,%3}, [%4];"
                 : "=r"(d0), "=r"(d1), "=r"(d2), "=r"(d3) : "r"(addr));
}
__device__ __forceinline__ void ldsm_x4_t(uint32_t& d0, uint32_t& d1, uint32_t& d2, uint32_t& d3,
                                          uint32_t addr) {
    asm volatile("ldmatrix.sync.aligned.m8n8.x4.trans.shared.b16 {%0,%1,%2,%3}, [%4];"
                 : "=r"(d0), "=r"(d1), "=r"(d2), "=r"(d3) : "r"(addr));
}
__device__ __forceinline__ void mma_f16(float& c0, float& c1, float& c2, float& c3,
                                        uint32_t a0, uint32_t a1, uint32_t a2, uint32_t a3,
                                        uint32_t b0, uint32_t b1) {
    asm volatile(
        "mma.sync.aligned.m16n8k16.row.col.f32.f16.f16.f32 "
        "{%0,%1,%2,%3}, {%4,%5,%6,%7}, {%8,%9}, {%0,%1,%2,%3};"
        : "+f"(c0), "+f"(c1), "+f"(c2), "+f"(c3)
        : "r"(a0), "r"(a1), "r"(a2), "r"(a3), "r"(b0), "r"(b1));
}

// ---------------- 1) gating (also clears inverse map) ----------------
__global__ void gate_kernel(const float* __restrict__ x, const float* __restrict__ wg)
{
    __shared__ float wgs[MDIM * 9];
    int tid = threadIdx.x;
    if (blockIdx.x < 32) g_inv[blockIdx.x * 256 + tid] = -1;
    for (int idx = tid; idx < MDIM * EEXP; idx += 256) {
        int m = idx >> 3, e = idx & 7;
        wgs[m * 9 + e] = wg[idx];
    }
    __syncthreads();

    int warp = tid >> 5, lane = tid & 31;
    int token = blockIdx.x * 8 + warp;
    if (token >= S_TOK) return;

    const float* xrow = x + (size_t)token * MDIM;
    float acc[EEXP];
#pragma unroll
    for (int e = 0; e < EEXP; e++) acc[e] = 0.f;
    for (int m = lane; m < MDIM; m += 32) {
        float xv = xrow[m];
        const float* w = &wgs[m * 9];
#pragma unroll
        for (int e = 0; e < EEXP; e++) acc[e] = fmaf(xv, w[e], acc[e]);
    }
#pragma unroll
    for (int e = 0; e < EEXP; e++) {
#pragma unroll
        for (int off = 16; off; off >>= 1)
            acc[e] += __shfl_xor_sync(0xFFFFFFFFu, acc[e], off);
    }
    if (lane == 0) {
        float mx = acc[0]; int best = 0;
#pragma unroll
        for (int e = 1; e < EEXP; e++) if (acc[e] > mx) { mx = acc[e]; best = e; }
        float denom = 0.f;
#pragma unroll
        for (int e = 0; e < EEXP; e++) denom += __expf(acc[e] - mx);
        g_eidx[token] = best;
        g_gate[token] = 1.0f / denom;
    }
}

// ---------------- 2) ordered per-expert scan: packed u64 shuffle scan ----------------
__global__ void scan_kernel()
{
    __shared__ unsigned long long s_lo[32], s_hi[32];
    const int t = threadIdx.x, lane = t & 31, warp = t >> 5;

    int loc[8];
    unsigned long long lo = 0, hi = 0;
    const int base_i = t * 8;
#pragma unroll
    for (int i = 0; i < 8; i++) {
        loc[i] = g_eidx[base_i + i];
        if (loc[i] < 4) lo += 1ull << (16 * loc[i]);
        else            hi += 1ull << (16 * (loc[i] - 4));
    }
    const unsigned long long mylo = lo, myhi = hi;

#pragma unroll
    for (int d = 1; d < 32; d <<= 1) {
        unsigned long long plo = __shfl_up_sync(0xFFFFFFFFu, lo, d);
        unsigned long long phi = __shfl_up_sync(0xFFFFFFFFu, hi, d);
        if (lane >= d) { lo += plo; hi += phi; }
    }
    if (lane == 31) { s_lo[warp] = lo; s_hi[warp] = hi; }
    __syncthreads();

    if (warp == 0) {
        unsigned long long wlo = s_lo[lane], whi = s_hi[lane];
#pragma unroll
        for (int d = 1; d < 32; d <<= 1) {
            unsigned long long plo = __shfl_up_sync(0xFFFFFFFFu, wlo, d);
            unsigned long long phi = __shfl_up_sync(0xFFFFFFFFu, whi, d);
            if (lane >= d) { wlo += plo; whi += phi; }
        }
        s_lo[lane] = wlo; s_hi[lane] = whi;
    }
    __syncthreads();

    const unsigned long long offlo = warp ? s_lo[warp - 1] : 0ull;
    const unsigned long long offhi = warp ? s_hi[warp - 1] : 0ull;
    const unsigned long long exlo = offlo + lo - mylo;
    const unsigned long long exhi = offhi + hi - myhi;

    int base[EEXP];
#pragma unroll
    for (int q = 0; q < 4; q++) {
        base[q]     = (int)((exlo >> (16 * q)) & 0xFFFFull);
        base[4 + q] = (int)((exhi >> (16 * q)) & 0xFFFFull);
    }
#pragma unroll
    for (int i = 0; i < 8; i++) {
        int tok = base_i + i;
        int e = loc[i];
        int pos = base[e]++;
        int keep = (pos < CAP);
        int pc = pos < CAP - 1 ? pos : CAP - 1;
        int slot = e * CAP + pc;
        g_gatef[tok] = keep ? g_gate[tok] : 0.0f;
        if (keep) g_inv[slot] = tok;
    }
}

// ---------------- 3) fill dispatch buffer (gather, fp32 -> fp16) ----------------
__global__ void fill_disp_kernel(const float* __restrict__ x)
{
    int slot = blockIdx.x;
    int t = threadIdx.x;          // 128 threads, 8 halves each
    int tok = g_inv[slot];
    uint4* dst = reinterpret_cast<uint4*>(reinterpret_cast<__half*>(g_disp) + (size_t)slot * MDIM) + t;
    if (tok < 0) {
        *dst = make_uint4(0u, 0u, 0u, 0u);
        return;
    }
    const float4* src = reinterpret_cast<const float4*>(x + (size_t)tok * MDIM) + t * 2;
    float4 v0 = src[0], v1 = src[1];
    __half2 h0 = __float22half2_rn(make_float2(v0.x, v0.y));
    __half2 h1 = __float22half2_rn(make_float2(v0.z, v0.w));
    __half2 h2 = __float22half2_rn(make_float2(v1.x, v1.y));
    __half2 h3 = __float22half2_rn(make_float2(v1.z, v1.w));
    uint4 o;
    o.x = *reinterpret_cast<uint32_t*>(&h0);
    o.y = *reinterpret_cast<uint32_t*>(&h1);
    o.z = *reinterpret_cast<uint32_t*>(&h2);
    o.w = *reinterpret_cast<uint32_t*>(&h3);
    *dst = o;
}

// ---------------- 4) zero output rows of dropped tokens ----------------
__global__ void zero_dropped_kernel(float* __restrict__ out)
{
    int tok = blockIdx.x;
    if (g_gatef[tok] != 0.0f) return;
    float4* dst = reinterpret_cast<float4*>(out + (size_t)tok * MDIM);
    dst[threadIdx.x] = make_float4(0.f, 0.f, 0.f, 0.f);
}

// ---------------- 5) fp32 -> fp16 weight convert ----------------
__global__ void cvt_w_kernel(const float* __restrict__ in, __half* __restrict__ outp, size_t n8)
{
    const float4* src = reinterpret_cast<const float4*>(in);
    uint4* dst = reinterpret_cast<uint4*>(outp);
    for (size_t i = blockIdx.x * blockDim.x + threadIdx.x; i < n8;
         i += (size_t)gridDim.x * blockDim.x) {
        float4 v0 = src[i * 2], v1 = src[i * 2 + 1];
        __half2 h0 = __float22half2_rn(make_float2(v0.x, v0.y));
        __half2 h1 = __float22half2_rn(make_float2(v0.z, v0.w));
        __half2 h2 = __float22half2_rn(make_float2(v1.x, v1.y));
        __half2 h3 = __float22half2_rn(make_float2(v1.z, v1.w));
        uint4 o;
        o.x = *reinterpret_cast<uint32_t*>(&h0);
        o.y = *reinterpret_cast<uint32_t*>(&h1);
        o.z = *reinterpret_cast<uint32_t*>(&h2);
        o.w = *reinterpret_cast<uint32_t*>(&h3);
        dst[i] = o;
    }
}

// ---------------- 6) fp16 mma.sync grouped GEMM ----------------
// CTA 128x128x32, 256 thr, 8 warps (2M x 4N), warp tile 64x32, 4-stage cp.async.cg.
// Single barrier per K-iter (prefetch issued right after the top barrier).
// MODE 0: h = relu(C) -> fp16.  MODE 1: out[g_inv[slot]] = C * g_gatef.
#define BK      32
#define A_STR   40
#define B_STR   136
#define A_STG   (128 * A_STR)            // 5120 halves
#define B_STG   (BK * B_STR)             // 4352 halves
#define STG_H   (A_STG + B_STG)          // 9472 halves / stage
#define NSTAGE  4
#define GEMM_SMEM (NSTAGE * STG_H * 2)   // 75776 bytes

template <int MODE>
__global__ __launch_bounds__(256, 2)
void gemm_f16(const __half* __restrict__ Ab, const __half* __restrict__ Bb,
              const float* __restrict__ biasb, void* __restrict__ Cb,
              int N, int K)
{
    extern __shared__ __half smh[];
    const int tid  = threadIdx.x;
    const int warp = tid >> 5, lane = tid & 31;
    const int g = lane >> 2, t = lane & 3;
    const int wm = warp >> 2, wn = warp & 3;
    const int e = blockIdx.z;
    const int rowBase = blockIdx.y * 128;
    const int colBase = blockIdx.x * 128;

    const __half* Ae = Ab + ((size_t)e * 1024 + rowBase) * K;
    const __half* Be = Bb + (size_t)e * K * N + colBase;
    const uint32_t smem_base = smem_u32(smh);

    float acc[4][4][4];
#pragma unroll
    for (int i = 0; i < 4; i++)
#pragma unroll
        for (int j = 0; j < 4; j++)
#pragma unroll
            for (int q = 0; q < 4; q++) acc[i][j][q] = 0.f;

    const int NK = K / BK;

    auto load_tile = [&](int kt, int stage) {
        const int k0 = kt * BK;
        const uint32_t sA = smem_base + (uint32_t)(stage * STG_H) * 2u;
        const uint32_t sB = sA + (uint32_t)A_STG * 2u;
#pragma unroll
        for (int it = 0; it < 2; it++) {
            int i = tid + it * 256;
            int r = i >> 2, c = i & 3;
            cp_async16(sA + (uint32_t)(r * A_STR + c * 8) * 2u,
                       Ae + (size_t)r * K + k0 + c * 8);
        }
#pragma unroll
        for (int it = 0; it < 2; it++) {
            int i = tid + it * 256;
            int r = i >> 4, c = i & 15;
            cp_async16(sB + (uint32_t)(r * B_STR + c * 8) * 2u,
                       Be + (size_t)(k0 + r) * N + c * 8);
        }
        cp_commit();
    };

    load_tile(0, 0);
    if (NK > 1) load_tile(1, 1);
    if (NK > 2) load_tile(2, 2);

    const int a_row = wm * 64 + (lane & 15);
    const int a_koff = (lane >> 4) * 8;
    const int b_krow = ((lane >> 3) & 1) * 8 + (lane & 7);
    const int b_noff = wn * 32 + (lane >> 4) * 8;

    for (int kt = 0; kt < NK; kt++) {
        cp_wait<2>();
        __syncthreads();

        // prefetch tile kt+3 into stage (kt+3)%4 == (kt-1)%4 (safe: consumed
        // at iter kt-1; this barrier ordered all its readers before us)
        if (kt + 3 < NK) load_tile(kt + 3, (kt + 3) % NSTAGE);
        else cp_commit();   // keep one group per iteration for wait accounting

        const int stage = kt % NSTAGE;
        const uint32_t sA = smem_base + (uint32_t)(stage * STG_H) * 2u;
        const uint32_t sB = sA + (uint32_t)A_STG * 2u;

#pragma unroll
        for (int ks = 0; ks < 2; ks++) {
            const int k0 = ks * 16;
            uint32_t a[4][4];
#pragma unroll
            for (int mf = 0; mf < 4; mf++)
                ldsm_x4(a[mf][0], a[mf][1], a[mf][2], a[mf][3],
                        sA + (uint32_t)((a_row + mf * 16) * A_STR + k0 + a_koff) * 2u);
            uint32_t b[4][2];
#pragma unroll
            for (int nb = 0; nb < 2; nb++)
                ldsm_x4_t(b[nb * 2][0], b[nb * 2][1], b[nb * 2 + 1][0], b[nb * 2 + 1][1],
                          sB + (uint32_t)((k0 + b_krow) * B_STR + b_noff + nb * 16) * 2u);
#pragma unroll
            for (int mf = 0; mf < 4; mf++)
#pragma unroll
                for (int nf = 0; nf < 4; nf++)
                    mma_f16(acc[mf][nf][0], acc[mf][nf][1], acc[mf][nf][2], acc[mf][nf][3],
                            a[mf][0], a[mf][1], a[mf][2], a[mf][3],
                            b[nf][0], b[nf][1]);
        }
        // no trailing barrier: next iteration's top barrier orders stage reuse
    }

    // epilogue
    const float* biasE = biasb + (size_t)e * N + colBase;
#pragma unroll
    for (int mf = 0; mf < 4; mf++) {
        const int r0 = wm * 64 + mf * 16 + g;           // rows r0 and r0+8 of CTA tile
#pragma unroll
        for (int rr = 0; rr < 2; rr++) {
            const int row = r0 + rr * 8;
            if (MODE == 0) {
                __half* C0 = reinterpret_cast<__half*>(Cb) +
                             ((size_t)e * 1024 + rowBase + row) * N + colBase;
#pragma unroll
                for (int nf = 0; nf < 4; nf++) {
                    const int col = wn * 32 + nf * 8 + 2 * t;
                    float v0 = fmaxf(acc[mf][nf][rr * 2 + 0] + biasE[col], 0.f);
                    float v1 = fmaxf(acc[mf][nf][rr * 2 + 1] + biasE[col + 1], 0.f);
                    *reinterpret_cast<__half2*>(C0 + col) =
                        __float22half2_rn(make_float2(v0, v1));
                }
            } else {
                const int slot = e * CAP + rowBase + row;
                const int tok = g_inv[slot];
                if (tok >= 0) {
                    const float gv = g_gatef[tok];
                    float* O0 = reinterpret_cast<float*>(Cb) +
                                (size_t)tok * MDIM + colBase;
#pragma unroll
                    for (int nf = 0; nf < 4; nf++) {
                        const int col = wn * 32 + nf * 8 + 2 * t;
                        float v0 = (acc[mf][nf][rr * 2 + 0] + biasE[col]) * gv;
                        float v1 = (acc[mf][nf][rr * 2 + 1] + biasE[col + 1]) * gv;
                        *reinterpret_cast<float2*>(O0 + col) = make_float2(v0, v1);
                    }
                }
            }
        }
    }
}

// ---------------- launch ----------------
extern "C" void kernel_launch(void* const* d_in, const int* in_sizes, int n_in,
                              void* d_out, int out_size)
{
    const float* x  = (const float*)d_in[0];
    const float* wg = (const float*)d_in[1];
    const float* w1 = (const float*)d_in[2];
    const float* b1 = (const float*)d_in[3];
    const float* w2 = (const float*)d_in[4];
    const float* b2 = (const float*)d_in[5];
    float* out = (float*)d_out;

    __half *disp, *h, *w1h, *w2h;
    cudaGetSymbolAddress((void**)&disp, g_disp);
    cudaGetSymbolAddress((void**)&h,    g_h);
    cudaGetSymbolAddress((void**)&w1h,  g_w1h);
    cudaGetSymbolAddress((void**)&w2h,  g_w2h);

    static cudaStream_t s2 = nullptr;
    static cudaEvent_t ev_fork = nullptr, ev_w1 = nullptr, ev_scan = nullptr, ev_w2z = nullptr;
    static bool init_done = false;
    if (!init_done) {
        cudaFuncSetAttribute(gemm_f16<0>,
                             cudaFuncAttributeMaxDynamicSharedMemorySize, GEMM_SMEM);
        cudaFuncSetAttribute(gemm_f16<1>,
                             cudaFuncAttributeMaxDynamicSharedMemorySize, GEMM_SMEM);
        cudaStreamCreateWithFlags(&s2, cudaStreamNonBlocking);
        cudaEventCreateWithFlags(&ev_fork, cudaEventDisableTiming);
        cudaEventCreateWithFlags(&ev_w1,   cudaEventDisableTiming);
        cudaEventCreateWithFlags(&ev_scan, cudaEventDisableTiming);
        cudaEventCreateWithFlags(&ev_w2z,  cudaEventDisableTiming);
        init_done = true;
    }

    // fork side stream
    cudaEventRecord(ev_fork, 0);
    cudaStreamWaitEvent(s2, ev_fork, 0);

    // side stream: w1 convert, then w2 convert (hidden under GEMM1)
    cvt_w_kernel<<<1024, 256, 0, s2>>>(w1, w1h, (size_t)EEXP * MDIM * HDIM / 8);
    cudaEventRecord(ev_w1, s2);
    cvt_w_kernel<<<1024, 256, 0, s2>>>(w2, w2h, (size_t)EEXP * HDIM * MDIM / 8);

    // main stream: gating chain
    gate_kernel<<<S_TOK / 8, 256>>>(x, wg);
    scan_kernel<<<1, 1024>>>();
    cudaEventRecord(ev_scan, 0);
    fill_disp_kernel<<<EEXP * CAP, 128>>>(x);

    // side stream: zero dropped rows of out (needs scan results)
    cudaStreamWaitEvent(s2, ev_scan, 0);
    zero_dropped_kernel<<<S_TOK, 256, 0, s2>>>(out);
    cudaEventRecord(ev_w2z, s2);

    // GEMM1 needs w1h only
    cudaStreamWaitEvent(0, ev_w1, 0);
    {
        dim3 grid(HDIM / 128, CAP / 128, EEXP);
        gemm_f16<0><<<grid, 256, GEMM_SMEM>>>(disp, w1h, b1, h, HDIM, MDIM);
    }
    // GEMM2 needs w2h + zeroed out
    cudaStreamWaitEvent(0, ev_w2z, 0);
    {
        dim3 grid(MDIM / 128, CAP / 128, EEXP);
        gemm_f16<1><<<grid, 256, GEMM_SMEM>>>(h, w2h, b2, out, MDIM, HDIM);
    }
}

// round 15
// speedup vs baseline: 1.0385x; 1.0385x over previous
#include <cuda_runtime.h>
#include <cuda_fp16.h>
#include <math.h>
#include <cstdint>

// Problem shape (fixed)
#define S_TOK 8192
#define MDIM  1024
#define EEXP  8
#define HDIM  4096
#define CAP   1024

// ---------------- device scratch ----------------
__device__ __half g_disp[EEXP * CAP * MDIM];            // 16 MB [E,C,M] fp16
__device__ __half g_h   [(size_t)EEXP * CAP * HDIM];    // 64 MB [E,C,H] fp16
__device__ __half g_w1h [(size_t)EEXP * MDIM * HDIM];   // 64 MB [E,K=M,N=H] fp16
__device__ __half g_w2h [(size_t)EEXP * HDIM * MDIM];   // 64 MB [E,K=H,N=M] fp16
__device__ int    g_eidx[S_TOK];
__device__ float  g_gate[S_TOK];
__device__ float  g_gatef[S_TOK];
__device__ int    g_inv [EEXP * CAP];                   // slot -> token (-1 empty)

// ---------------- helpers ----------------
__device__ __forceinline__ uint32_t smem_u32(const void* p) {
    uint32_t a;
    asm("{ .reg .u64 t; cvta.to.shared.u64 t, %1; cvt.u32.u64 %0, t; }" : "=r"(a) : "l"(p));
    return a;
}
__device__ __forceinline__ void cp_async16(uint32_t dst, const void* src) {
    asm volatile("cp.async.ca.shared.global [%0], [%1], 16;" :: "r"(dst), "l"(src) : "memory");
}
__device__ __forceinline__ void cp_commit() {
    asm volatile("cp.async.commit_group;" ::: "memory");
}
template <int N>
__device__ __forceinline__ void cp_wait() {
    asm volatile("cp.async.wait_group %0;" :: "n"(N) : "memory");
}
__device__ __forceinline__ void ldsm_x4(uint32_t& d0, uint32_t& d1, uint32_t& d2, uint32_t& d3,
                                        uint32_t addr) {
    asm volatile("ldmatrix.sync.aligned.m8n8.x4.shared.b16 {%0,%1,%2,%3}, [%4];"
                 : "=r"(d0), "=r"(d1), "=r"(d2), "=r"(d3) : "r"(addr));
}
__device__ __forceinline__ void ldsm_x4_t(uint32_t& d0, uint32_t& d1, uint32_t& d2, uint32_t& d3,
                                          uint32_t addr) {
    asm volatile("ldmatrix.sync.aligned.m8n8.x4.trans.shared.b16 {%0,%1,%2,%3}, [%4];"
                 : "=r"(d0), "=r"(d1), "=r"(d2), "=r"(d3) : "r"(addr));
}
__device__ __forceinline__ void mma_f16(float& c0, float& c1, float& c2, float& c3,
                                        uint32_t a0, uint32_t a1, uint32_t a2, uint32_t a3,
                                        uint32_t b0, uint32_t b1) {
    asm volatile(
        "mma.sync.aligned.m16n8k16.row.col.f32.f16.f16.f32 "
        "{%0,%1,%2,%3}, {%4,%5,%6,%7}, {%8,%9}, {%0,%1,%2,%3};"
        : "+f"(c0), "+f"(c1), "+f"(c2), "+f"(c3)
        : "r"(a0), "r"(a1), "r"(a2), "r"(a3), "r"(b0), "r"(b1));
}

// ---------------- 1) gating (also clears inverse map) ----------------
__global__ void gate_kernel(const float* __restrict__ x, const float* __restrict__ wg)
{
    __shared__ float wgs[MDIM * 9];
    int tid = threadIdx.x;
    if (blockIdx.x < 32) g_inv[blockIdx.x * 256 + tid] = -1;
    for (int idx = tid; idx < MDIM * EEXP; idx += 256) {
        int m = idx >> 3, e = idx & 7;
        wgs[m * 9 + e] = wg[idx];
    }
    __syncthreads();

    int warp = tid >> 5, lane = tid & 31;
    int token = blockIdx.x * 8 + warp;
    if (token >= S_TOK) return;

    const float* xrow = x + (size_t)token * MDIM;
    float acc[EEXP];
#pragma unroll
    for (int e = 0; e < EEXP; e++) acc[e] = 0.f;
    for (int m = lane; m < MDIM; m += 32) {
        float xv = xrow[m];
        const float* w = &wgs[m * 9];
#pragma unroll
        for (int e = 0; e < EEXP; e++) acc[e] = fmaf(xv, w[e], acc[e]);
    }
#pragma unroll
    for (int e = 0; e < EEXP; e++) {
#pragma unroll
        for (int off = 16; off; off >>= 1)
            acc[e] += __shfl_xor_sync(0xFFFFFFFFu, acc[e], off);
    }
    if (lane == 0) {
        float mx = acc[0]; int best = 0;
#pragma unroll
        for (int e = 1; e < EEXP; e++) if (acc[e] > mx) { mx = acc[e]; best = e; }
        float denom = 0.f;
#pragma unroll
        for (int e = 0; e < EEXP; e++) denom += __expf(acc[e] - mx);
        g_eidx[token] = best;
        g_gate[token] = 1.0f / denom;
    }
}

// ---------------- 2) ordered per-expert scan: packed u64 shuffle scan ----------------
__global__ void scan_kernel()
{
    __shared__ unsigned long long s_lo[32], s_hi[32];
    const int t = threadIdx.x, lane = t & 31, warp = t >> 5;

    int loc[8];
    unsigned long long lo = 0, hi = 0;
    const int base_i = t * 8;
#pragma unroll
    for (int i = 0; i < 8; i++) {
        loc[i] = g_eidx[base_i + i];
        if (loc[i] < 4) lo += 1ull << (16 * loc[i]);
        else            hi += 1ull << (16 * (loc[i] - 4));
    }
    const unsigned long long mylo = lo, myhi = hi;

#pragma unroll
    for (int d = 1; d < 32; d <<= 1) {
        unsigned long long plo = __shfl_up_sync(0xFFFFFFFFu, lo, d);
        unsigned long long phi = __shfl_up_sync(0xFFFFFFFFu, hi, d);
        if (lane >= d) { lo += plo; hi += phi; }
    }
    if (lane == 31) { s_lo[warp] = lo; s_hi[warp] = hi; }
    __syncthreads();

    if (warp == 0) {
        unsigned long long wlo = s_lo[lane], whi = s_hi[lane];
#pragma unroll
        for (int d = 1; d < 32; d <<= 1) {
            unsigned long long plo = __shfl_up_sync(0xFFFFFFFFu, wlo, d);
            unsigned long long phi = __shfl_up_sync(0xFFFFFFFFu, whi, d);
            if (lane >= d) { wlo += plo; whi += phi; }
        }
        s_lo[lane] = wlo; s_hi[lane] = whi;
    }
    __syncthreads();

    const unsigned long long offlo = warp ? s_lo[warp - 1] : 0ull;
    const unsigned long long offhi = warp ? s_hi[warp - 1] : 0ull;
    const unsigned long long exlo = offlo + lo - mylo;
    const unsigned long long exhi = offhi + hi - myhi;

    int base[EEXP];
#pragma unroll
    for (int q = 0; q < 4; q++) {
        base[q]     = (int)((exlo >> (16 * q)) & 0xFFFFull);
        base[4 + q] = (int)((exhi >> (16 * q)) & 0xFFFFull);
    }
#pragma unroll
    for (int i = 0; i < 8; i++) {
        int tok = base_i + i;
        int e = loc[i];
        int pos = base[e]++;
        int keep = (pos < CAP);
        int pc = pos < CAP - 1 ? pos : CAP - 1;
        int slot = e * CAP + pc;
        g_gatef[tok] = keep ? g_gate[tok] : 0.0f;
        if (keep) g_inv[slot] = tok;
    }
}

// ---------------- 3) fill dispatch buffer (gather, fp32 -> fp16) ----------------
__global__ void fill_disp_kernel(const float* __restrict__ x)
{
    int slot = blockIdx.x;
    int t = threadIdx.x;          // 128 threads, 8 halves each
    int tok = g_inv[slot];
    uint4* dst = reinterpret_cast<uint4*>(reinterpret_cast<__half*>(g_disp) + (size_t)slot * MDIM) + t;
    if (tok < 0) {
        *dst = make_uint4(0u, 0u, 0u, 0u);
        return;
    }
    const float4* src = reinterpret_cast<const float4*>(x + (size_t)tok * MDIM) + t * 2;
    float4 v0 = src[0], v1 = src[1];
    __half2 h0 = __float22half2_rn(make_float2(v0.x, v0.y));
    __half2 h1 = __float22half2_rn(make_float2(v0.z, v0.w));
    __half2 h2 = __float22half2_rn(make_float2(v1.x, v1.y));
    __half2 h3 = __float22half2_rn(make_float2(v1.z, v1.w));
    uint4 o;
    o.x = *reinterpret_cast<uint32_t*>(&h0);
    o.y = *reinterpret_cast<uint32_t*>(&h1);
    o.z = *reinterpret_cast<uint32_t*>(&h2);
    o.w = *reinterpret_cast<uint32_t*>(&h3);
    *dst = o;
}

// ---------------- 4) zero output rows of dropped tokens ----------------
__global__ void zero_dropped_kernel(float* __restrict__ out)
{
    int tok = blockIdx.x;
    if (g_gatef[tok] != 0.0f) return;
    float4* dst = reinterpret_cast<float4*>(out + (size_t)tok * MDIM);
    dst[threadIdx.x] = make_float4(0.f, 0.f, 0.f, 0.f);
}

// ---------------- 5) fp32 -> fp16 weight convert ----------------
__global__ void cvt_w_kernel(const float* __restrict__ in, __half* __restrict__ outp, size_t n8)
{
    const float4* src = reinterpret_cast<const float4*>(in);
    uint4* dst = reinterpret_cast<uint4*>(outp);
    for (size_t i = blockIdx.x * blockDim.x + threadIdx.x; i < n8;
         i += (size_t)gridDim.x * blockDim.x) {
        float4 v0 = src[i * 2], v1 = src[i * 2 + 1];
        __half2 h0 = __float22half2_rn(make_float2(v0.x, v0.y));
        __half2 h1 = __float22half2_rn(make_float2(v0.z, v0.w));
        __half2 h2 = __float22half2_rn(make_float2(v1.x, v1.y));
        __half2 h3 = __float22half2_rn(make_float2(v1.z, v1.w));
        uint4 o;
        o.x = *reinterpret_cast<uint32_t*>(&h0);
        o.y = *reinterpret_cast<uint32_t*>(&h1);
        o.z = *reinterpret_cast<uint32_t*>(&h2);
        o.w = *reinterpret_cast<uint32_t*>(&h3);
        dst[i] = o;
    }
}

// ---------------- 6) fp16 mma.sync grouped GEMM ----------------
// CTA 128x128x32, 256 thr, 8 warps (2M x 4N), warp tile 64x32, 4-stage cp.async.ca.
// Single barrier per K-iter (prefetch issued right after the top barrier).
// MODE 0: h = relu(C) -> fp16.  MODE 1: out[g_inv[slot]] = C * g_gatef.
#define BK      32
#define A_STR   40
#define B_STR   136
#define A_STG   (128 * A_STR)            // 5120 halves
#define B_STG   (BK * B_STR)             // 4352 halves
#define STG_H   (A_STG + B_STG)          // 9472 halves / stage
#define NSTAGE  4
#define GEMM_SMEM (NSTAGE * STG_H * 2)   // 75776 bytes

template <int MODE>
__global__ __launch_bounds__(256, 2)
void gemm_f16(const __half* __restrict__ Ab, const __half* __restrict__ Bb,
              const float* __restrict__ biasb, void* __restrict__ Cb,
              int N, int K)
{
    extern __shared__ __half smh[];
    const int tid  = threadIdx.x;
    const int warp = tid >> 5, lane = tid & 31;
    const int g = lane >> 2, t = lane & 3;
    const int wm = warp >> 2, wn = warp & 3;
    const int e = blockIdx.z;
    const int rowBase = blockIdx.y * 128;
    const int colBase = blockIdx.x * 128;

    const __half* Ae = Ab + ((size_t)e * 1024 + rowBase) * K;
    const __half* Be = Bb + (size_t)e * K * N + colBase;
    const uint32_t smem_base = smem_u32(smh);

    float acc[4][4][4];
#pragma unroll
    for (int i = 0; i < 4; i++)
#pragma unroll
        for (int j = 0; j < 4; j++)
#pragma unroll
            for (int q = 0; q < 4; q++) acc[i][j][q] = 0.f;

    const int NK = K / BK;

    auto load_tile = [&](int kt, int stage) {
        const int k0 = kt * BK;
        const uint32_t sA = smem_base + (uint32_t)(stage * STG_H) * 2u;
        const uint32_t sB = sA + (uint32_t)A_STG * 2u;
#pragma unroll
        for (int it = 0; it < 2; it++) {
            int i = tid + it * 256;
            int r = i >> 2, c = i & 3;
            cp_async16(sA + (uint32_t)(r * A_STR + c * 8) * 2u,
                       Ae + (size_t)r * K + k0 + c * 8);
        }
#pragma unroll
        for (int it = 0; it < 2; it++) {
            int i = tid + it * 256;
            int r = i >> 4, c = i & 15;
            cp_async16(sB + (uint32_t)(r * B_STR + c * 8) * 2u,
                       Be + (size_t)(k0 + r) * N + c * 8);
        }
        cp_commit();
    };

    load_tile(0, 0);
    if (NK > 1) load_tile(1, 1);
    if (NK > 2) load_tile(2, 2);

    const int a_row = wm * 64 + (lane & 15);
    const int a_koff = (lane >> 4) * 8;
    const int b_krow = ((lane >> 3) & 1) * 8 + (lane & 7);
    const int b_noff = wn * 32 + (lane >> 4) * 8;

    for (int kt = 0; kt < NK; kt++) {
        cp_wait<2>();
        __syncthreads();

        // prefetch tile kt+3 into stage (kt+3)%4 == (kt-1)%4 (safe: consumed
        // at iter kt-1; this barrier ordered all its readers before us)
        if (kt + 3 < NK) load_tile(kt + 3, (kt + 3) % NSTAGE);
        else cp_commit();   // keep one group per iteration for wait accounting

        const int stage = kt % NSTAGE;
        const uint32_t sA = smem_base + (uint32_t)(stage * STG_H) * 2u;
        const uint32_t sB = sA + (uint32_t)A_STG * 2u;

#pragma unroll
        for (int ks = 0; ks < 2; ks++) {
            const int k0 = ks * 16;
            uint32_t a[4][4];
#pragma unroll
            for (int mf = 0; mf < 4; mf++)
                ldsm_x4(a[mf][0], a[mf][1], a[mf][2], a[mf][3],
                        sA + (uint32_t)((a_row + mf * 16) * A_STR + k0 + a_koff) * 2u);
            uint32_t b[4][2];
#pragma unroll
            for (int nb = 0; nb < 2; nb++)
                ldsm_x4_t(b[nb * 2][0], b[nb * 2][1], b[nb * 2 + 1][0], b[nb * 2 + 1][1],
                          sB + (uint32_t)((k0 + b_krow) * B_STR + b_noff + nb * 16) * 2u);
#pragma unroll
            for (int mf = 0; mf < 4; mf++)
#pragma unroll
                for (int nf = 0; nf < 4; nf++)
                    mma_f16(acc[mf][nf][0], acc[mf][nf][1], acc[mf][nf][2], acc[mf][nf][3],
                            a[mf][0], a[mf][1], a[mf][2], a[mf][3],
                            b[nf][0], b[nf][1]);
        }
        // no trailing barrier: next iteration's top barrier orders stage reuse
    }

    // epilogue
    const float* biasE = biasb + (size_t)e * N + colBase;
#pragma unroll
    for (int mf = 0; mf < 4; mf++) {
        const int r0 = wm * 64 + mf * 16 + g;           // rows r0 and r0+8 of CTA tile
#pragma unroll
        for (int rr = 0; rr < 2; rr++) {
            const int row = r0 + rr * 8;
            if (MODE == 0) {
                __half* C0 = reinterpret_cast<__half*>(Cb) +
                             ((size_t)e * 1024 + rowBase + row) * N + colBase;
#pragma unroll
                for (int nf = 0; nf < 4; nf++) {
                    const int col = wn * 32 + nf * 8 + 2 * t;
                    float v0 = fmaxf(acc[mf][nf][rr * 2 + 0] + biasE[col], 0.f);
                    float v1 = fmaxf(acc[mf][nf][rr * 2 + 1] + biasE[col + 1], 0.f);
                    *reinterpret_cast<__half2*>(C0 + col) =
                        __float22half2_rn(make_float2(v0, v1));
                }
            } else {
                const int slot = e * CAP + rowBase + row;
                const int tok = g_inv[slot];
                if (tok >= 0) {
                    const float gv = g_gatef[tok];
                    float* O0 = reinterpret_cast<float*>(Cb) +
                                (size_t)tok * MDIM + colBase;
#pragma unroll
                    for (int nf = 0; nf < 4; nf++) {
                        const int col = wn * 32 + nf * 8 + 2 * t;
                        float v0 = (acc[mf][nf][rr * 2 + 0] + biasE[col]) * gv;
                        float v1 = (acc[mf][nf][rr * 2 + 1] + biasE[col + 1]) * gv;
                        *reinterpret_cast<float2*>(O0 + col) = make_float2(v0, v1);
                    }
                }
            }
        }
    }
}

// ---------------- launch ----------------
extern "C" void kernel_launch(void* const* d_in, const int* in_sizes, int n_in,
                              void* d_out, int out_size)
{
    const float* x  = (const float*)d_in[0];
    const float* wg = (const float*)d_in[1];
    const float* w1 = (const float*)d_in[2];
    const float* b1 = (const float*)d_in[3];
    const float* w2 = (const float*)d_in[4];
    const float* b2 = (const float*)d_in[5];
    float* out = (float*)d_out;

    __half *disp, *h, *w1h, *w2h;
    cudaGetSymbolAddress((void**)&disp, g_disp);
    cudaGetSymbolAddress((void**)&h,    g_h);
    cudaGetSymbolAddress((void**)&w1h,  g_w1h);
    cudaGetSymbolAddress((void**)&w2h,  g_w2h);

    static cudaStream_t s2 = nullptr;
    static cudaEvent_t ev_fork = nullptr, ev_w1 = nullptr, ev_scan = nullptr, ev_w2z = nullptr;
    static bool init_done = false;
    if (!init_done) {
        cudaFuncSetAttribute(gemm_f16<0>,
                             cudaFuncAttributeMaxDynamicSharedMemorySize, GEMM_SMEM);
        cudaFuncSetAttribute(gemm_f16<1>,
                             cudaFuncAttributeMaxDynamicSharedMemorySize, GEMM_SMEM);
        cudaStreamCreateWithFlags(&s2, cudaStreamNonBlocking);
        cudaEventCreateWithFlags(&ev_fork, cudaEventDisableTiming);
        cudaEventCreateWithFlags(&ev_w1,   cudaEventDisableTiming);
        cudaEventCreateWithFlags(&ev_scan, cudaEventDisableTiming);
        cudaEventCreateWithFlags(&ev_w2z,  cudaEventDisableTiming);
        init_done = true;
    }

    // fork side stream
    cudaEventRecord(ev_fork, 0);
    cudaStreamWaitEvent(s2, ev_fork, 0);

    // side stream: w1 convert, then w2 convert (hidden under GEMM1)
    cvt_w_kernel<<<1024, 256, 0, s2>>>(w1, w1h, (size_t)EEXP * MDIM * HDIM / 8);
    cudaEventRecord(ev_w1, s2);
    cvt_w_kernel<<<1024, 256, 0, s2>>>(w2, w2h, (size_t)EEXP * HDIM * MDIM / 8);

    // main stream: gating chain
    gate_kernel<<<S_TOK / 8, 256>>>(x, wg);
    scan_kernel<<<1, 1024>>>();
    cudaEventRecord(ev_scan, 0);
    fill_disp_kernel<<<EEXP * CAP, 128>>>(x);

    // side stream: zero dropped rows of out (needs scan results)
    cudaStreamWaitEvent(s2, ev_scan, 0);
    zero_dropped_kernel<<<S_TOK, 256, 0, s2>>>(out);
    cudaEventRecord(ev_w2z, s2);

    // GEMM1 needs w1h only
    cudaStreamWaitEvent(0, ev_w1, 0);
    {
        dim3 grid(HDIM / 128, CAP / 128, EEXP);
        gemm_f16<0><<<grid, 256, GEMM_SMEM>>>(disp, w1h, b1, h, HDIM, MDIM);
    }
    // GEMM2 needs w2h + zeroed out
    cudaStreamWaitEvent(0, ev_w2z, 0);
    {
        dim3 grid(MDIM / 128, CAP / 128, EEXP);
        gemm_f16<1><<<grid, 256, GEMM_SMEM>>>(h, w2h, b2, out, MDIM, HDIM);
    }
}